// round 10
// baseline (speedup 1.0000x reference)
#include <cuda_runtime.h>

typedef unsigned long long ull;

#define D_IN   992
#define HID    32
#define W1     6
#define NB     12
#define KC     16               // k per tile
#define RPB    256              // rows per block
#define NTHR   128
#define NTILES 62               // 62*16 = 992
#define ASTR   388              // words per k-row of As (padded-block layout)
#define WSTR   36               // words per k-row of Ws

__device__ __forceinline__ ull ffma2(ull a, ull b, ull c) {
    ull d;
    asm("fma.rn.f32x2 %0, %1, %2, %3;" : "=l"(d) : "l"(a), "l"(b), "l"(c));
    return d;
}
__device__ __forceinline__ ull dup64(float a) {
    ull d;
    asm("mov.b64 %0, {%1, %1};" : "=l"(d) : "f"(a));
    return d;
}

// padded-block row map: 8-row groups + 4-word pad -> lane bank bases 12m mod 32
// cover all 8 bank-groups; linear inside aligned 8-blocks (order-preserving).
__device__ __forceinline__ int Pmap(int r) { return r + ((r >> 3) << 2); }

// Compact degree-4 uniform B-spline: 5 nonzero values + masked clamped indices.
__device__ __forceinline__ void basis5m(float x, float Bv[5], int ix[5]) {
    float u  = (x + 2.0f) * 4.0f;
    float fj = floorf(u);
    int   j0 = (int)fj;
    float s  = u - fj;
    float B0, B1, B2, B3, B4;
    B1 = s;  B0 = 1.0f - s;
    B2 = 0.5f * (s * B1);
    B1 = 0.5f * ((s + 1.0f) * B0 + (2.0f - s) * B1);
    B0 = 0.5f * ((1.0f - s) * B0);
    const float i3 = (1.0f / 3.0f);
    B3 = i3 * (s * B2);
    B2 = i3 * ((s + 1.0f) * B1 + (3.0f - s) * B2);
    B1 = i3 * ((s + 2.0f) * B0 + (2.0f - s) * B1);
    B0 = i3 * ((1.0f - s) * B0);
    B4 = 0.25f * (s * B3);
    B3 = 0.25f * ((s + 1.0f) * B2 + (4.0f - s) * B3);
    B2 = 0.25f * ((s + 2.0f) * B1 + (3.0f - s) * B2);
    B1 = 0.25f * ((s + 3.0f) * B0 + (2.0f - s) * B1);
    B0 = 0.25f * ((1.0f - s) * B0);
    const bool vr = (j0 >= 0) && (j0 < 16);
    float Bt[5] = {B0, B1, B2, B3, B4};
    #pragma unroll
    for (int m = 0; m < 5; m++) {
        int  id = j0 - 4 + m;
        bool v  = vr && (id >= 0) && (id < 12);
        ix[m] = v ? id : 0;
        Bv[m] = v ? Bt[m] : 0.0f;
    }
}

__device__ __forceinline__ float silu_f(float x) {
    return x / (1.0f + __expf(-x));
}

// smem byte offsets
#define WS_OFF   24832           // after As (16*388*4)
#define GEMM_REG 33792           // params start after the Hs alias region
#define SMEM_SZ  44352

__global__ __launch_bounds__(NTHR, 3)
void kan_fused_kernel(const float* __restrict__ node_rep,
                      const float* __restrict__ mlp_w,
                      const float* __restrict__ mlp_b,
                      const float* __restrict__ coef0,
                      const float* __restrict__ wb0,
                      const float* __restrict__ ws0,
                      const float* __restrict__ b0,
                      const float* __restrict__ coef1,
                      const float* __restrict__ wb1,
                      const float* __restrict__ ws1,
                      const float* __restrict__ b1,
                      float* __restrict__ out, int n)
{
    __shared__ __align__(16) char smem[SMEM_SZ];
    float* As = (float*)smem;                        // [16][388] (transposed, padded-block)
    float* Ws = (float*)(smem + WS_OFF);             // [16][36]  (row-major W tile)
    float (*Hs)[HID + 1] = (float (*)[HID + 1])smem; // [256][33] alias (post-GEMM)
    float* csc0T = (float*)(smem + GEMM_REG);        // [12][193]: [b*193 + i*6 + o]
    float* wb0s  = csc0T + 2316;                     // [32*6]
    float* csc1T = wb0s + 192;                       // [12][7]:  [b*7 + i]
    float* wb1s  = csc1T + 84;                       // [6]
    float* b0s   = wb1s + 6;                         // [6]
    float* mlpbs = b0s + 6;                          // [32]
    float* b1s   = mlpbs + 32;                       // [1]

    const int tid  = threadIdx.x;
    const int w    = tid >> 5;
    const int l    = tid & 31;
    const int row0 = blockIdx.x * RPB;

    // ---- stage params (prescaled, gather-transposed with odd strides) ----
    for (int idx = tid; idx < NB * HID * W1; idx += NTHR) {
        int b = idx / (HID * W1), r = idx % (HID * W1);
        int i = r / W1, o = r % W1;
        csc0T[b * 193 + r] = coef0[i * (W1 * NB) + o * NB + b] * ws0[r];
    }
    for (int idx = tid; idx < HID * W1; idx += NTHR)
        wb0s[idx] = wb0[idx];
    if (tid < NB * 7) {
        int b = tid / 7, i = tid % 7;
        if (i < W1) csc1T[tid] = coef1[i * NB + b] * ws1[i];
    }
    if (tid < W1) { wb1s[tid] = wb1[tid]; b0s[tid] = b0[tid]; }
    if (tid < HID) mlpbs[tid] = mlp_b[tid];
    if (tid == 0) b1s[0] = b1[0];

    // ---- GEMM geometry: warp w -> rows [w*64, w*64+64) ----
    const int rg = (tid >> 2) & 7;      // 8-row group
    const int cq = tid & 3;             // 8-col group (cols cq*8 .. +7)
    const int R0 = w * 64 + rg * 8;
    // padded-block physical bases for the two k-swizzle states (XOR row bit4)
    const int base0 = Pmap(R0);
    const int base1 = Pmap(R0 ^ 16);

    ull acc[8][4];                      // [row][colpair] f32x2; 64 regs
    #pragma unroll
    for (int r = 0; r < 8; r++)
        #pragma unroll
        for (int p = 0; p < 4; p++) acc[r][p] = 0ull;

    // ---- stager coordinates ----
    const int sr = w * 8 + (l >> 2);    // staging base row (rows sr + 32j)
    const int k4 = l & 3;               // 4-k chunk within tile (k = k4*4+q)
    const int wk = tid >> 3;            // W: k row (0..15)
    const int wc = tid & 7;             // W: float4 chunk (cols wc*4..+3)
    const int s1 = ((k4 >> 1) & 1) << 4; // store swizzle: XOR row bit4, keyed on bit3 of k

    float4 pa[8];
    float4 pw;

    // prologue: prefetch tile 0
    #pragma unroll
    for (int j = 0; j < 8; j++) {
        int gr = row0 + sr + 32 * j;
        pa[j] = make_float4(0.f, 0.f, 0.f, 0.f);
        if (gr < n)
            pa[j] = *(const float4*)&node_rep[(size_t)gr * D_IN + k4 * 4];
    }
    pw = *(const float4*)&mlp_w[(size_t)wk * HID + wc * 4];

    for (int t = 0; t < NTILES; t++) {
        __syncthreads();                 // previous tile's compute done
        // ---- STS A transposed (conflict-free: bank bases {0,16,24,8}+i) ----
        {
            const int kb = k4 * 4;
            #pragma unroll
            for (int j = 0; j < 8; j++) {
                int rw = (sr + 32 * j) ^ s1;
                int pp = Pmap(rw);
                As[(kb + 0) * ASTR + pp] = pa[j].x;
                As[(kb + 1) * ASTR + pp] = pa[j].y;
                As[(kb + 2) * ASTR + pp] = pa[j].z;
                As[(kb + 3) * ASTR + pp] = pa[j].w;
            }
        }
        // ---- STS W row-major ----
        *(float4*)&Ws[wk * WSTR + wc * 4] = pw;
        __syncthreads();

        // ---- prefetch next tile ----
        if (t + 1 < NTILES) {
            const int kc = (t + 1) * KC;
            #pragma unroll
            for (int j = 0; j < 8; j++) {
                int gr = row0 + sr + 32 * j;
                float4 v = make_float4(0.f, 0.f, 0.f, 0.f);
                if (gr < n)
                    v = *(const float4*)&node_rep[(size_t)gr * D_IN + kc + k4 * 4];
                pa[j] = v;
            }
            pw = *(const float4*)&mlp_w[(size_t)(kc + wk) * HID + wc * 4];
        }

        // ---- compute 16 k: per k 4 conflict-free LDS.128 + 8 dups + 32 FFMA2 ----
        #pragma unroll
        for (int k = 0; k < KC; k++) {
            const float* ab = &As[k * ASTR + (((k >> 3) & 1) ? base1 : base0)];
            float4 a0 = *(const float4*)ab;
            float4 a1 = *(const float4*)(ab + 4);
            ull ad0 = dup64(a0.x), ad1 = dup64(a0.y), ad2 = dup64(a0.z), ad3 = dup64(a0.w);
            ull ad4 = dup64(a1.x), ad5 = dup64(a1.y), ad6 = dup64(a1.z), ad7 = dup64(a1.w);
            const ull* wbp = (const ull*)&Ws[k * WSTR] + cq * 4;
            ulonglong2 wA = *(const ulonglong2*)(wbp);
            ulonglong2 wB = *(const ulonglong2*)(wbp + 2);
            acc[0][0] = ffma2(ad0, wA.x, acc[0][0]);
            acc[0][1] = ffma2(ad0, wA.y, acc[0][1]);
            acc[0][2] = ffma2(ad0, wB.x, acc[0][2]);
            acc[0][3] = ffma2(ad0, wB.y, acc[0][3]);
            acc[1][0] = ffma2(ad1, wA.x, acc[1][0]);
            acc[1][1] = ffma2(ad1, wA.y, acc[1][1]);
            acc[1][2] = ffma2(ad1, wB.x, acc[1][2]);
            acc[1][3] = ffma2(ad1, wB.y, acc[1][3]);
            acc[2][0] = ffma2(ad2, wA.x, acc[2][0]);
            acc[2][1] = ffma2(ad2, wA.y, acc[2][1]);
            acc[2][2] = ffma2(ad2, wB.x, acc[2][2]);
            acc[2][3] = ffma2(ad2, wB.y, acc[2][3]);
            acc[3][0] = ffma2(ad3, wA.x, acc[3][0]);
            acc[3][1] = ffma2(ad3, wA.y, acc[3][1]);
            acc[3][2] = ffma2(ad3, wB.x, acc[3][2]);
            acc[3][3] = ffma2(ad3, wB.y, acc[3][3]);
            acc[4][0] = ffma2(ad4, wA.x, acc[4][0]);
            acc[4][1] = ffma2(ad4, wA.y, acc[4][1]);
            acc[4][2] = ffma2(ad4, wB.x, acc[4][2]);
            acc[4][3] = ffma2(ad4, wB.y, acc[4][3]);
            acc[5][0] = ffma2(ad5, wA.x, acc[5][0]);
            acc[5][1] = ffma2(ad5, wA.y, acc[5][1]);
            acc[5][2] = ffma2(ad5, wB.x, acc[5][2]);
            acc[5][3] = ffma2(ad5, wB.y, acc[5][3]);
            acc[6][0] = ffma2(ad6, wA.x, acc[6][0]);
            acc[6][1] = ffma2(ad6, wA.y, acc[6][1]);
            acc[6][2] = ffma2(ad6, wB.x, acc[6][2]);
            acc[6][3] = ffma2(ad6, wB.y, acc[6][3]);
            acc[7][0] = ffma2(ad7, wA.x, acc[7][0]);
            acc[7][1] = ffma2(ad7, wA.y, acc[7][1]);
            acc[7][2] = ffma2(ad7, wB.x, acc[7][2]);
            acc[7][3] = ffma2(ad7, wB.y, acc[7][3]);
        }
    }
    __syncthreads();   // GEMM SMEM dead; safe to overwrite with Hs

    // ---- epilogue: acc -> Hs (+bias) ----
    #pragma unroll
    for (int r = 0; r < 8; r++) {
        #pragma unroll
        for (int p = 0; p < 4; p++) {
            const int col = cq * 8 + 2 * p;
            Hs[R0 + r][col    ] = __uint_as_float((unsigned)(acc[r][p]      )) + mlpbs[col];
            Hs[R0 + r][col + 1] = __uint_as_float((unsigned)(acc[r][p] >> 32)) + mlpbs[col + 1];
        }
    }
    __syncthreads();

    // ---- KAN: each thread owns 2 full rows end-to-end ----
    #pragma unroll 1
    for (int rr = tid; rr < RPB; rr += NTHR) {
        const int grow = row0 + rr;
        float acc6[W1] = {0.f, 0.f, 0.f, 0.f, 0.f, 0.f};
        #pragma unroll 1
        for (int i = 0; i < HID; i++) {
            float x = Hs[rr][i];
            float Bv[5]; int ix[5];
            basis5m(x, Bv, ix);
            float s = silu_f(x);
            const int base = i * W1;
            int a0 = ix[0] * 193 + base, a1 = ix[1] * 193 + base,
                a2 = ix[2] * 193 + base, a3 = ix[3] * 193 + base,
                a4 = ix[4] * 193 + base;
            #pragma unroll
            for (int o = 0; o < W1; o++) {
                float d =      Bv[0] * csc0T[a0 + o];
                d = fmaf(Bv[1], csc0T[a1 + o], d);
                d = fmaf(Bv[2], csc0T[a2 + o], d);
                d = fmaf(Bv[3], csc0T[a3 + o], d);
                d = fmaf(Bv[4], csc0T[a4 + o], d);
                acc6[o] = fmaf(s, wb0s[base + o], acc6[o] + d);
            }
        }
        float res = b1s[0];
        #pragma unroll 1
        for (int i = 0; i < W1; i++) {
            float x = acc6[i] + b0s[i];
            float Bv[5]; int ix[5];
            basis5m(x, Bv, ix);
            float d =      Bv[0] * csc1T[ix[0] * 7 + i];
            d = fmaf(Bv[1], csc1T[ix[1] * 7 + i], d);
            d = fmaf(Bv[2], csc1T[ix[2] * 7 + i], d);
            d = fmaf(Bv[3], csc1T[ix[3] * 7 + i], d);
            d = fmaf(Bv[4], csc1T[ix[4] * 7 + i], d);
            res += d + silu_f(x) * wb1s[i];
        }
        if (grow < n) out[grow] = res;
    }
}

extern "C" void kernel_launch(void* const* d_in, const int* in_sizes, int n_in,
                              void* d_out, int out_size) {
    const float* node_rep = (const float*)d_in[0];
    const float* mlp_w    = (const float*)d_in[1];
    const float* mlp_b    = (const float*)d_in[2];
    const float* coef0    = (const float*)d_in[3];
    const float* wb0      = (const float*)d_in[4];
    const float* ws0      = (const float*)d_in[5];
    const float* b0       = (const float*)d_in[6];
    const float* coef1    = (const float*)d_in[7];
    const float* wb1      = (const float*)d_in[8];
    const float* ws1      = (const float*)d_in[9];
    const float* b1       = (const float*)d_in[10];

    int n = out_size;                       // 300000 rows, one output each
    int grid = (n + RPB - 1) / RPB;
    kan_fused_kernel<<<grid, NTHR>>>(node_rep, mlp_w, mlp_b, coef0, wb0, ws0,
                                     b0, coef1, wb1, ws1, b1,
                                     (float*)d_out, n);
}